// round 4
// baseline (speedup 1.0000x reference)
#include <cuda_runtime.h>
#include <cuda_fp16.h>
#include <cstdint>

#define NN 50000
#define F  256
#define KW 3

// Scratch (no cudaMalloc allowed).
__device__ __half g_xh[(size_t)NN * F];
__device__ __half g_T1[(size_t)NN * F];
__device__ __half g_T2[(size_t)NN * F];
__device__ __half g_wh[(size_t)KW * F * F];
__device__ int    g_rp[NN + 1];

// ---------------------------------------------------------------------------
// Prep: one launch does x->fp16, W->fp16, and row_ptr (block-range split).
//   blocks [0, XB)          : cvt x        (XB = N*F/4/256)
//   blocks [XB, XB+WB)      : cvt weight   (WB = 3*F*F/4/256)
//   blocks [XB+WB, ...)     : rowptr lower_bound
// ---------------------------------------------------------------------------
__global__ void prep_kernel(const float* __restrict__ x,
                            const float* __restrict__ wgt,
                            const int* __restrict__ erow,
                            int E, int N, int XB, int WB) {
    int b = blockIdx.x;
    if (b < XB + WB) {
        const float* src = (b < XB) ? x : wgt;
        __half* dst      = (b < XB) ? g_xh : g_wh;
        int i = (b < XB ? b : b - XB) * 256 + threadIdx.x;
        int n4 = (b < XB) ? N * F / 4 : KW * F * F / 4;
        if (i < n4) {
            float4 v = *reinterpret_cast<const float4*>(src + (size_t)i * 4);
            __half2 h0 = __floats2half2_rn(v.x, v.y);
            __half2 h1 = __floats2half2_rn(v.z, v.w);
            uint2 o;
            o.x = *reinterpret_cast<uint32_t*>(&h0);
            o.y = *reinterpret_cast<uint32_t*>(&h1);
            *reinterpret_cast<uint2*>(dst + (size_t)i * 4) = o;
        }
    } else {
        int i = (b - XB - WB) * 256 + threadIdx.x;
        if (i > N) return;
        int lo = 0, hi = E;
        while (lo < hi) {
            int mid = (lo + hi) >> 1;
            if (erow[mid] < i) lo = mid + 1; else hi = mid;
        }
        g_rp[i] = lo;
    }
}

// ---------------------------------------------------------------------------
// GEMM tile helpers (fp16 mma m16n8k16, cp.async double-buffered, 128x128xK256)
// ---------------------------------------------------------------------------
#define GBM 128
#define GBN 128
#define GBK 32
#define PA  40
#define PB  136

__device__ __forceinline__ void cp16(uint32_t dst, const void* src, int sz) {
    asm volatile("cp.async.cg.shared.global [%0], [%1], 16, %2;\n"
                 :: "r"(dst), "l"(src), "r"(sz));
}
__device__ __forceinline__ void ldsm_x4(uint32_t r[4], uint32_t addr) {
    asm volatile("ldmatrix.sync.aligned.m8n8.x4.shared.b16 {%0,%1,%2,%3}, [%4];"
                 : "=r"(r[0]), "=r"(r[1]), "=r"(r[2]), "=r"(r[3]) : "r"(addr));
}
__device__ __forceinline__ void ldsm_x4_t(uint32_t r[4], uint32_t addr) {
    asm volatile("ldmatrix.sync.aligned.m8n8.x4.trans.shared.b16 {%0,%1,%2,%3}, [%4];"
                 : "=r"(r[0]), "=r"(r[1]), "=r"(r[2]), "=r"(r[3]) : "r"(addr));
}

__device__ __forceinline__ void accum8(float acc[8], uint4 v, float w) {
    const __half2* h = reinterpret_cast<const __half2*>(&v);
    #pragma unroll
    for (int q = 0; q < 4; ++q) {
        float2 f = __half22float2(h[q]);
        acc[2 * q]     = fmaf(w, f.x, acc[2 * q]);
        acc[2 * q + 1] = fmaf(w, f.y, acc[2 * q + 1]);
    }
}

// ---------------------------------------------------------------------------
// Fused phase kernel.
//   PHASE 0: blocks [0,NG) gemm out  = bias + xh@W0 ; blocks [NG,..) spmm T1=L xh
//   PHASE 1: blocks [0,NG) gemm out += T1@W1        ; blocks [NG,..) spmm T2=2LT1-xh
//   PHASE 2: gemm out += T2@W2 (grid = NG only)
// ---------------------------------------------------------------------------
template <int PHASE>
__global__ __launch_bounds__(256, 4)
void phase_kernel(const int* __restrict__ ecol, const float* __restrict__ ew,
                  const float* __restrict__ bias, float* __restrict__ out,
                  int N, int NG) {
    __shared__ __half sA[2][GBM * PA];
    __shared__ __half sB[2][GBK * PB];

    int tid  = threadIdx.x;
    int warp = tid >> 5, lane = tid & 31;

    if (PHASE == 2 || (int)blockIdx.x < NG) {
        // ================= GEMM path =================
        int tile = blockIdx.x;
        int col0 = (tile & 1) * GBN;
        int row0 = (tile >> 1) * GBM;
        const __half* asrc = (PHASE == 0) ? g_xh : (PHASE == 1) ? g_T1 : g_T2;
        const __half* wsrc = g_wh + (size_t)PHASE * F * F;
        int wm = (warp >> 1) * 32;
        int wn = (warp & 1) * 64;

        float acc[2][8][4];
        #pragma unroll
        for (int mi = 0; mi < 2; ++mi)
            #pragma unroll
            for (int ni = 0; ni < 8; ++ni)
                #pragma unroll
                for (int q = 0; q < 4; ++q) acc[mi][ni][q] = 0.f;

        uint32_t aBase = (uint32_t)__cvta_generic_to_shared(&sA[0][0]);
        uint32_t bBase = (uint32_t)__cvta_generic_to_shared(&sB[0][0]);
        const uint32_t aStage = GBM * PA * 2;
        const uint32_t bStage = GBK * PB * 2;

        auto issue = [&](int s, int iter) {
            int colA = iter * GBK;
            #pragma unroll
            for (int it = 0; it < 2; ++it) {
                int idx = tid + it * 256;
                int r = idx >> 2, c = idx & 3;
                int grow = row0 + r;
                const __half* g = asrc + (size_t)min(grow, NN - 1) * 256 + colA + c * 8;
                cp16(aBase + s * aStage + (uint32_t)(r * PA + c * 8) * 2, g,
                     grow < N ? 16 : 0);
            }
            #pragma unroll
            for (int it = 0; it < 2; ++it) {
                int idx = tid + it * 256;
                int k = idx >> 4, c = idx & 15;
                const __half* g = wsrc + (size_t)(colA + k) * 256 + col0 + c * 8;
                cp16(bBase + s * bStage + (uint32_t)(k * PB + c * 8) * 2, g, 16);
            }
        };

        issue(0, 0);
        asm volatile("cp.async.commit_group;");

        for (int iter = 0; iter < 8; ++iter) {
            int s = iter & 1;
            if (iter + 1 < 8) {
                issue(s ^ 1, iter + 1);
                asm volatile("cp.async.commit_group;");
                asm volatile("cp.async.wait_group 1;");
            } else {
                asm volatile("cp.async.wait_group 0;");
            }
            __syncthreads();

            uint32_t aS = aBase + s * aStage;
            uint32_t bS = bBase + s * bStage;
            #pragma unroll
            for (int kc = 0; kc < 2; ++kc) {
                uint32_t a[2][4], b[4][4];
                #pragma unroll
                for (int mi = 0; mi < 2; ++mi) {
                    int r = wm + mi * 16 + (lane & 15);
                    ldsm_x4(a[mi], aS + (uint32_t)(r * PA + kc * 16 + (lane >> 4) * 8) * 2);
                }
                #pragma unroll
                for (int bi = 0; bi < 4; ++bi) {
                    int k = kc * 16 + (lane & 15);
                    ldsm_x4_t(b[bi], bS + (uint32_t)(k * PB + wn + bi * 16 + (lane >> 4) * 8) * 2);
                }
                #pragma unroll
                for (int mi = 0; mi < 2; ++mi)
                    #pragma unroll
                    for (int ni = 0; ni < 8; ++ni) {
                        uint32_t b0 = b[ni >> 1][(ni & 1) * 2];
                        uint32_t b1 = b[ni >> 1][(ni & 1) * 2 + 1];
                        asm volatile(
                            "mma.sync.aligned.m16n8k16.row.col.f32.f16.f16.f32 "
                            "{%0,%1,%2,%3}, {%4,%5,%6,%7}, {%8,%9}, {%0,%1,%2,%3};"
                            : "+f"(acc[mi][ni][0]), "+f"(acc[mi][ni][1]),
                              "+f"(acc[mi][ni][2]), "+f"(acc[mi][ni][3])
                            : "r"(a[mi][0]), "r"(a[mi][1]), "r"(a[mi][2]), "r"(a[mi][3]),
                              "r"(b0), "r"(b1));
                    }
            }
            __syncthreads();
        }

        int g = lane >> 2, t = lane & 3;
        #pragma unroll
        for (int ni = 0; ni < 8; ++ni) {
            int col = col0 + wn + ni * 8 + t * 2;
            float b0 = 0.f, b1 = 0.f;
            if (PHASE == 0) { b0 = __ldg(bias + col); b1 = __ldg(bias + col + 1); }
            #pragma unroll
            for (int mi = 0; mi < 2; ++mi) {
                #pragma unroll
                for (int h = 0; h < 2; ++h) {
                    int row = row0 + wm + mi * 16 + g + h * 8;
                    if (row < N) {
                        float2* p = reinterpret_cast<float2*>(out + (size_t)row * 256 + col);
                        float2 v;
                        if (PHASE == 0) {
                            v = make_float2(acc[mi][ni][2 * h] + b0, acc[mi][ni][2 * h + 1] + b1);
                        } else {
                            float2 o = *p;
                            v = make_float2(o.x + acc[mi][ni][2 * h], o.y + acc[mi][ni][2 * h + 1]);
                        }
                        *p = v;
                    }
                }
            }
        }
    } else {
        // ================= SpMM path =================
        int node = ((int)blockIdx.x - NG) * 8 + warp;
        if (node >= NN) return;

        const uint4* __restrict__ src =
            reinterpret_cast<const uint4*>((PHASE == 0) ? g_xh : g_T1);
        __half* dst = (PHASE == 0) ? g_T1 : g_T2;

        int r0 = g_rp[node], r1 = g_rp[node + 1];
        float acc[8];
        #pragma unroll
        for (int q = 0; q < 8; ++q) acc[q] = 0.f;

        for (int base = r0; base < r1; base += 32) {
            int cnt = min(32, r1 - base);
            int   c  = 0;
            float wv = 0.f;
            if (base + lane < r1) {
                c  = ecol[base + lane];
                wv = ew[base + lane];
            }
            int j = 0;
            for (; j + 4 <= cnt; j += 4) {
                int   c0 = __shfl_sync(0xffffffffu, c,  j);
                int   c1 = __shfl_sync(0xffffffffu, c,  j + 1);
                int   c2 = __shfl_sync(0xffffffffu, c,  j + 2);
                int   c3 = __shfl_sync(0xffffffffu, c,  j + 3);
                float w0 = __shfl_sync(0xffffffffu, wv, j);
                float w1 = __shfl_sync(0xffffffffu, wv, j + 1);
                float w2 = __shfl_sync(0xffffffffu, wv, j + 2);
                float w3 = __shfl_sync(0xffffffffu, wv, j + 3);
                uint4 v0 = __ldg(&src[(size_t)c0 * 32 + lane]);
                uint4 v1 = __ldg(&src[(size_t)c1 * 32 + lane]);
                uint4 v2 = __ldg(&src[(size_t)c2 * 32 + lane]);
                uint4 v3 = __ldg(&src[(size_t)c3 * 32 + lane]);
                accum8(acc, v0, w0);
                accum8(acc, v1, w1);
                accum8(acc, v2, w2);
                accum8(acc, v3, w3);
            }
            for (; j < cnt; ++j) {
                int   cj = __shfl_sync(0xffffffffu, c,  j);
                float wj = __shfl_sync(0xffffffffu, wv, j);
                uint4 v = __ldg(&src[(size_t)cj * 32 + lane]);
                accum8(acc, v, wj);
            }
        }

        if (PHASE == 1) {
            uint4 xv = reinterpret_cast<const uint4*>(g_xh)[(size_t)node * 32 + lane];
            const __half2* h = reinterpret_cast<const __half2*>(&xv);
            #pragma unroll
            for (int q = 0; q < 4; ++q) {
                float2 f = __half22float2(h[q]);
                acc[2 * q]     = 2.f * acc[2 * q]     - f.x;
                acc[2 * q + 1] = 2.f * acc[2 * q + 1] - f.y;
            }
        }

        __half2 o[4];
        #pragma unroll
        for (int q = 0; q < 4; ++q) o[q] = __floats2half2_rn(acc[2 * q], acc[2 * q + 1]);
        reinterpret_cast<uint4*>(dst)[(size_t)node * 32 + lane] =
            *reinterpret_cast<uint4*>(o);
    }
}

// ---------------------------------------------------------------------------
extern "C" void kernel_launch(void* const* d_in, const int* in_sizes, int n_in,
                              void* d_out, int out_size) {
    const float* x    = (const float*)d_in[0];
    const int*   erow = (const int*)  d_in[1];
    const int*   ecol = (const int*)  d_in[2];
    const float* ew   = (const float*)d_in[3];
    const float* wgt  = (const float*)d_in[4];
    const float* bias = (const float*)d_in[5];
    float* out = (float*)d_out;

    int N = in_sizes[0] / F;   // 50000
    int E = in_sizes[1];       // 1600000

    int XB = (N * F / 4 + 255) / 256;          // 3125
    int WB = (KW * F * F / 4 + 255) / 256;     // 192
    int RB = (N + 1 + 255) / 256;              // 196
    prep_kernel<<<XB + WB + RB, 256>>>(x, wgt, erow, E, N, XB, WB);

    int NG = 2 * ((N + GBM - 1) / GBM);        // 782
    int NS = (N + 7) / 8;                      // 6250

    phase_kernel<0><<<NG + NS, 256>>>(ecol, ew, bias, out, N, NG);
    phase_kernel<1><<<NG + NS, 256>>>(ecol, ew, bias, out, N, NG);
    phase_kernel<2><<<NG,      256>>>(ecol, ew, bias, out, N, NG);
}

// round 5
// speedup vs baseline: 1.8556x; 1.8556x over previous
#include <cuda_runtime.h>
#include <cuda_fp16.h>
#include <cstdint>

#define NN 50000
#define F  256
#define KW 3

// Scratch (no cudaMalloc allowed).
__device__ __half g_xh[(size_t)NN * F];
__device__ __half g_T1[(size_t)NN * F];
__device__ __half g_T2[(size_t)NN * F];
__device__ __half g_wh[(size_t)KW * F * F];
__device__ int    g_rp[NN + 1];

// ---------------------------------------------------------------------------
// Prep: one launch does x->fp16, W->fp16, and row_ptr (block-range split).
// ---------------------------------------------------------------------------
__global__ void prep_kernel(const float* __restrict__ x,
                            const float* __restrict__ wgt,
                            const int* __restrict__ erow,
                            int E, int N, int XB, int WB) {
    int b = blockIdx.x;
    if (b < XB + WB) {
        const float* src = (b < XB) ? x : wgt;
        __half* dst      = (b < XB) ? g_xh : g_wh;
        int i = (b < XB ? b : b - XB) * 256 + threadIdx.x;
        int n4 = (b < XB) ? N * F / 4 : KW * F * F / 4;
        if (i < n4) {
            float4 v = *reinterpret_cast<const float4*>(src + (size_t)i * 4);
            __half2 h0 = __floats2half2_rn(v.x, v.y);
            __half2 h1 = __floats2half2_rn(v.z, v.w);
            uint2 o;
            o.x = *reinterpret_cast<uint32_t*>(&h0);
            o.y = *reinterpret_cast<uint32_t*>(&h1);
            *reinterpret_cast<uint2*>(dst + (size_t)i * 4) = o;
        }
    } else {
        int i = (b - XB - WB) * 256 + threadIdx.x;
        if (i > N) return;
        int lo = 0, hi = E;
        while (lo < hi) {
            int mid = (lo + hi) >> 1;
            if (erow[mid] < i) lo = mid + 1; else hi = mid;
        }
        g_rp[i] = lo;
    }
}

// ---------------------------------------------------------------------------
// SpMM (exact R2 structure; measured at the LTS gather ceiling).
// Warp per node row; lane l owns features [8l, 8l+8) as one uint4 (8 fp16).
// MODE 0: g_T1 = L @ g_xh        MODE 1: g_T2 = 2*(L @ g_T1) - g_xh
// ---------------------------------------------------------------------------
__device__ __forceinline__ void accum8(float acc[8], uint4 v, float w) {
    const __half2* h = reinterpret_cast<const __half2*>(&v);
    #pragma unroll
    for (int q = 0; q < 4; ++q) {
        float2 f = __half22float2(h[q]);
        acc[2 * q]     = fmaf(w, f.x, acc[2 * q]);
        acc[2 * q + 1] = fmaf(w, f.y, acc[2 * q + 1]);
    }
}

template <int MODE>
__global__ __launch_bounds__(256)
void spmm_h_kernel(const int* __restrict__ ecol, const float* __restrict__ ew) {
    int warp = threadIdx.x >> 5, lane = threadIdx.x & 31;
    int node = blockIdx.x * 8 + warp;
    if (node >= NN) return;

    const uint4* __restrict__ src =
        reinterpret_cast<const uint4*>((MODE == 0) ? g_xh : g_T1);
    __half* dst = (MODE == 0) ? g_T1 : g_T2;

    int r0 = g_rp[node], r1 = g_rp[node + 1];
    float acc[8];
    #pragma unroll
    for (int q = 0; q < 8; ++q) acc[q] = 0.f;

    for (int base = r0; base < r1; base += 32) {
        int cnt = min(32, r1 - base);
        int   c  = 0;
        float wv = 0.f;
        if (base + lane < r1) {
            c  = ecol[base + lane];
            wv = ew[base + lane];
        }
        int j = 0;
        for (; j + 4 <= cnt; j += 4) {
            int   c0 = __shfl_sync(0xffffffffu, c,  j);
            int   c1 = __shfl_sync(0xffffffffu, c,  j + 1);
            int   c2 = __shfl_sync(0xffffffffu, c,  j + 2);
            int   c3 = __shfl_sync(0xffffffffu, c,  j + 3);
            float w0 = __shfl_sync(0xffffffffu, wv, j);
            float w1 = __shfl_sync(0xffffffffu, wv, j + 1);
            float w2 = __shfl_sync(0xffffffffu, wv, j + 2);
            float w3 = __shfl_sync(0xffffffffu, wv, j + 3);
            uint4 v0 = __ldg(&src[(size_t)c0 * 32 + lane]);
            uint4 v1 = __ldg(&src[(size_t)c1 * 32 + lane]);
            uint4 v2 = __ldg(&src[(size_t)c2 * 32 + lane]);
            uint4 v3 = __ldg(&src[(size_t)c3 * 32 + lane]);
            accum8(acc, v0, w0);
            accum8(acc, v1, w1);
            accum8(acc, v2, w2);
            accum8(acc, v3, w3);
        }
        for (; j < cnt; ++j) {
            int   cj = __shfl_sync(0xffffffffu, c,  j);
            float wj = __shfl_sync(0xffffffffu, wv, j);
            uint4 v = __ldg(&src[(size_t)cj * 32 + lane]);
            accum8(acc, v, wj);
        }
    }

    if (MODE == 1) {
        uint4 xv = reinterpret_cast<const uint4*>(g_xh)[(size_t)node * 32 + lane];
        const __half2* h = reinterpret_cast<const __half2*>(&xv);
        #pragma unroll
        for (int q = 0; q < 4; ++q) {
            float2 f = __half22float2(h[q]);
            acc[2 * q]     = 2.f * acc[2 * q]     - f.x;
            acc[2 * q + 1] = 2.f * acc[2 * q + 1] - f.y;
        }
    }

    __half2 o[4];
    #pragma unroll
    for (int q = 0; q < 4; ++q) o[q] = __floats2half2_rn(acc[2 * q], acc[2 * q + 1]);
    reinterpret_cast<uint4*>(dst)[(size_t)node * 32 + lane] =
        *reinterpret_cast<uint4*>(o);
}

// ---------------------------------------------------------------------------
// GEMM: out[N,256] = [xh|T1|T2](N x 768) @ Wh(768 x 256) + bias
// BM=128, BN=256 (full width -> A read exactly once), BK=32, 512 threads,
// 16 warps as 4M x 4N, warp tile 32x64. fp16 mma m16n8k16, cp.async 2-stage.
// Pitches PA=40, PB=264 halves: odd multiples of 16B -> conflict-free ldmatrix.
// ---------------------------------------------------------------------------
#define GBM 128
#define GBN 256
#define GBK 32
#define PA  40
#define PB  264
#define ASTG (GBM * PA)            // halves per A stage
#define BSTG (GBK * PB)            // halves per B stage
#define SMEM_HALVES (2 * ASTG + 2 * BSTG)

__device__ __forceinline__ void cp16(uint32_t dst, const void* src, int sz) {
    asm volatile("cp.async.cg.shared.global [%0], [%1], 16, %2;\n"
                 :: "r"(dst), "l"(src), "r"(sz));
}
__device__ __forceinline__ void ldsm_x4(uint32_t r[4], uint32_t addr) {
    asm volatile("ldmatrix.sync.aligned.m8n8.x4.shared.b16 {%0,%1,%2,%3}, [%4];"
                 : "=r"(r[0]), "=r"(r[1]), "=r"(r[2]), "=r"(r[3]) : "r"(addr));
}
__device__ __forceinline__ void ldsm_x4_t(uint32_t r[4], uint32_t addr) {
    asm volatile("ldmatrix.sync.aligned.m8n8.x4.trans.shared.b16 {%0,%1,%2,%3}, [%4];"
                 : "=r"(r[0]), "=r"(r[1]), "=r"(r[2]), "=r"(r[3]) : "r"(addr));
}

__global__ __launch_bounds__(512, 1)
void gemm_h_kernel(const float* __restrict__ bias, float* __restrict__ out, int N) {
    extern __shared__ __half sm[];

    int tid  = threadIdx.x;
    int warp = tid >> 5, lane = tid & 31;
    int row0 = blockIdx.x * GBM;
    int wm = (warp >> 2) * 32;       // 4 warps along M
    int wn = (warp & 3) * 64;        // 4 warps along N

    float acc[2][8][4];
    #pragma unroll
    for (int mi = 0; mi < 2; ++mi)
        #pragma unroll
        for (int ni = 0; ni < 8; ++ni)
            #pragma unroll
            for (int q = 0; q < 4; ++q) acc[mi][ni][q] = 0.f;

    uint32_t base  = (uint32_t)__cvta_generic_to_shared(sm);
    uint32_t aBase = base;
    uint32_t bBase = base + 2 * ASTG * 2;

    auto issue = [&](int s, int iter) {
        const __half* asrc = (iter < 8) ? g_xh : (iter < 16) ? g_T1 : g_T2;
        int colA = (iter * GBK) & 255;
        {
            int r = tid >> 2, c = tid & 3;
            int grow = row0 + r;
            const __half* g = asrc + (size_t)min(grow, NN - 1) * 256 + colA + c * 8;
            cp16(aBase + (uint32_t)(s * ASTG + r * PA + c * 8) * 2, g,
                 grow < N ? 16 : 0);
        }
        int kb = iter * GBK;
        #pragma unroll
        for (int it = 0; it < 2; ++it) {
            int idx = tid + it * 512;
            int k = idx >> 5, c = idx & 31;
            const __half* g = g_wh + (size_t)(kb + k) * 256 + c * 8;
            cp16(bBase + (uint32_t)(s * BSTG + k * PB + c * 8) * 2, g, 16);
        }
    };

    issue(0, 0);
    asm volatile("cp.async.commit_group;");

    for (int iter = 0; iter < 24; ++iter) {
        int s = iter & 1;
        if (iter + 1 < 24) {
            issue(s ^ 1, iter + 1);
            asm volatile("cp.async.commit_group;");
            asm volatile("cp.async.wait_group 1;");
        } else {
            asm volatile("cp.async.wait_group 0;");
        }
        __syncthreads();

        uint32_t aS = aBase + (uint32_t)(s * ASTG) * 2;
        uint32_t bS = bBase + (uint32_t)(s * BSTG) * 2;
        #pragma unroll
        for (int kc = 0; kc < 2; ++kc) {
            uint32_t a[2][4], b[4][4];
            #pragma unroll
            for (int mi = 0; mi < 2; ++mi) {
                int r = wm + mi * 16 + (lane & 15);
                ldsm_x4(a[mi], aS + (uint32_t)(r * PA + kc * 16 + (lane >> 4) * 8) * 2);
            }
            #pragma unroll
            for (int bi = 0; bi < 4; ++bi) {
                int k = kc * 16 + (lane & 15);
                ldsm_x4_t(b[bi], bS + (uint32_t)(k * PB + wn + bi * 16 + (lane >> 4) * 8) * 2);
            }
            #pragma unroll
            for (int mi = 0; mi < 2; ++mi)
                #pragma unroll
                for (int ni = 0; ni < 8; ++ni) {
                    uint32_t b0 = b[ni >> 1][(ni & 1) * 2];
                    uint32_t b1 = b[ni >> 1][(ni & 1) * 2 + 1];
                    asm volatile(
                        "mma.sync.aligned.m16n8k16.row.col.f32.f16.f16.f32 "
                        "{%0,%1,%2,%3}, {%4,%5,%6,%7}, {%8,%9}, {%0,%1,%2,%3};"
                        : "+f"(acc[mi][ni][0]), "+f"(acc[mi][ni][1]),
                          "+f"(acc[mi][ni][2]), "+f"(acc[mi][ni][3])
                        : "r"(a[mi][0]), "r"(a[mi][1]), "r"(a[mi][2]), "r"(a[mi][3]),
                          "r"(b0), "r"(b1));
                }
        }
        __syncthreads();
    }

    int g = lane >> 2, t = lane & 3;
    #pragma unroll
    for (int ni = 0; ni < 8; ++ni) {
        int col = wn + ni * 8 + t * 2;
        float b0 = __ldg(bias + col), b1 = __ldg(bias + col + 1);
        #pragma unroll
        for (int mi = 0; mi < 2; ++mi) {
            int row = row0 + wm + mi * 16 + g;
            if (row < N) {
                float2 v = make_float2(acc[mi][ni][0] + b0, acc[mi][ni][1] + b1);
                *reinterpret_cast<float2*>(out + (size_t)row * 256 + col) = v;
            }
            if (row + 8 < N) {
                float2 v = make_float2(acc[mi][ni][2] + b0, acc[mi][ni][3] + b1);
                *reinterpret_cast<float2*>(out + (size_t)(row + 8) * 256 + col) = v;
            }
        }
    }
}

// ---------------------------------------------------------------------------
extern "C" void kernel_launch(void* const* d_in, const int* in_sizes, int n_in,
                              void* d_out, int out_size) {
    const float* x    = (const float*)d_in[0];
    const int*   erow = (const int*)  d_in[1];
    const int*   ecol = (const int*)  d_in[2];
    const float* ew   = (const float*)d_in[3];
    const float* wgt  = (const float*)d_in[4];
    const float* bias = (const float*)d_in[5];
    float* out = (float*)d_out;

    int N = in_sizes[0] / F;   // 50000
    int E = in_sizes[1];       // 1600000

    int XB = (N * F / 4 + 255) / 256;
    int WB = (KW * F * F / 4 + 255) / 256;
    int RB = (N + 1 + 255) / 256;
    prep_kernel<<<XB + WB + RB, 256>>>(x, wgt, erow, E, N, XB, WB);

    spmm_h_kernel<0><<<(N + 7) / 8, 256>>>(ecol, ew);   // T1 = L xh
    spmm_h_kernel<1><<<(N + 7) / 8, 256>>>(ecol, ew);   // T2 = 2 L T1 - xh

    static int smem_set = 0;
    if (!smem_set) {
        cudaFuncSetAttribute(gemm_h_kernel,
                             cudaFuncAttributeMaxDynamicSharedMemorySize,
                             SMEM_HALVES * 2);
        smem_set = 1;
    }
    gemm_h_kernel<<<(N + GBM - 1) / GBM, 512, SMEM_HALVES * 2>>>(bias, out, N);
}